// round 4
// baseline (speedup 1.0000x reference)
#include <cuda_runtime.h>
#include <math.h>
#include <stdint.h>

#define SEQL 256
#define BATCH 64
#define HID 1024
#define GATES 4096
#define MROWS (SEQL*BATCH)      // 16384
#define BH (BATCH*HID)          // 65536

// ---------------- scratch (device globals; no cudaMalloc allowed) ----------
__device__ float g_xp[(size_t)MROWS * GATES];   // 256 MB: x-projection for one layer
__device__ float g_ys[(size_t)SEQL * BH];       // 64 MB: layer-0 h history
__device__ float g_hb[2 * BH];                  // layer-1 h ping-pong
__device__ volatile unsigned g_bar_gen;
__device__ unsigned g_bar_cnt;

// ---------------- helpers ---------------------------------------------------
__device__ __forceinline__ uint32_t f2tf32(float x) {
    uint32_t r; asm("cvt.rna.tf32.f32 %0, %1;" : "=r"(r) : "f"(x)); return r;
}
__device__ __forceinline__ void mma8(float* d, const uint32_t* a, const uint32_t* b) {
    asm volatile(
        "mma.sync.aligned.m16n8k8.row.col.f32.tf32.tf32.f32 "
        "{%0,%1,%2,%3},{%4,%5,%6,%7},{%8,%9},{%0,%1,%2,%3};"
        : "+f"(d[0]), "+f"(d[1]), "+f"(d[2]), "+f"(d[3])
        : "r"(a[0]), "r"(a[1]), "r"(a[2]), "r"(a[3]), "r"(b[0]), "r"(b[1]));
}
__device__ __forceinline__ void cpa16(uint32_t s, const void* g) {
    asm volatile("cp.async.cg.shared.global [%0], [%1], 16;" :: "r"(s), "l"(g));
}
#define CP_COMMIT() asm volatile("cp.async.commit_group;")
#define CP_WAIT(n)  asm volatile("cp.async.wait_group %0;" :: "n"(n))

__device__ __forceinline__ float sigf(float x) { return __fdividef(1.f, 1.f + __expf(-x)); }
__device__ __forceinline__ float tanhfast(float x) { return __fdividef(2.f, 1.f + __expf(-2.f * x)) - 1.f; }

// ---------------- grid barrier (all 128 blocks resident, 1/SM) --------------
__device__ __forceinline__ void gridbar(unsigned nblk) {
    __threadfence();
    __syncthreads();
    if (threadIdx.x == 0) {
        unsigned gen = g_bar_gen;
        if (atomicAdd(&g_bar_cnt, 1u) == nblk - 1u) {
            atomicExch(&g_bar_cnt, 0u);
            __threadfence();
            g_bar_gen = gen + 1u;
        } else {
            while (g_bar_gen == gen) { __nanosleep(32); }
            __threadfence();
        }
    }
    __syncthreads();
}

// ---------------- tf32 SGEMM v3: cp.async 2-stage pipelined ------------------
// C[M][4096] = gather(A)[M][1024] @ W^T + b1 + b2
// block 128x128, k-chunk 32, 256 threads (8 warps 2x4), warp tile 64x32.
// SMEM: 2 stages x [As 128x32 | Ws 128x32] fp32, XOR swizzle: elem (m,k) at
// m*32 + (k ^ ((m&7)<<2)). Fragments cvt.rna'd to tf32 in registers.
#define STG 8192   // floats per stage (As 4096 + Ws 4096)
__global__ __launch_bounds__(256, 2) void sgemm_xp(
    const float* __restrict__ A, const int* __restrict__ gidx,
    const float* __restrict__ W,
    const float* __restrict__ b1, const float* __restrict__ b2,
    float* __restrict__ C)
{
    extern __shared__ float smf[];
    const uint32_t smem_b = (uint32_t)__cvta_generic_to_shared(smf);
    const int bn = blockIdx.x * 128;
    const int bm = blockIdx.y * 128;
    const int tid = threadIdx.x;
    const int warp = tid >> 5, lane = tid & 31;
    const int g = lane >> 2, tig = lane & 3;
    const int wm = warp >> 2, wn = warp & 3;

    // per-thread copy assignment: 4 (m,j) pairs for A and W each
    int cm[4]; int cj[4]; int arow[4]; uint32_t adst[4], wdst[4];
#pragma unroll
    for (int rep = 0; rep < 4; rep++) {
        int q = tid + rep * 256;
        int m = q >> 3, j = q & 7;
        cm[rep] = m; cj[rep] = j;
        arow[rep] = gidx ? gidx[bm + m] : (bm + m);
        uint32_t off = (uint32_t)(m * 32 + ((4 * j) ^ ((m & 7) << 2)));
        adst[rep] = smem_b + off * 4;
        wdst[rep] = smem_b + (off + 4096) * 4;
    }

    float acc[4][4][4];
#pragma unroll
    for (int mi = 0; mi < 4; mi++)
#pragma unroll
        for (int ni = 0; ni < 4; ni++)
#pragma unroll
            for (int r = 0; r < 4; r++) acc[mi][ni][r] = 0.f;

    // prologue: stage chunk 0 into buffer 0
#pragma unroll
    for (int rep = 0; rep < 4; rep++) {
        cpa16(adst[rep], A + (size_t)arow[rep] * 1024 + 4 * cj[rep]);
        cpa16(wdst[rep], W + (size_t)(bn + cm[rep]) * 1024 + 4 * cj[rep]);
    }
    CP_COMMIT();

    const int swz = g << 2;
    for (int c = 0; c < 32; c++) {
        if (c + 1 < 32) {
            uint32_t so = (uint32_t)(((c + 1) & 1) * STG) * 4;
            int kc = (c + 1) * 32;
#pragma unroll
            for (int rep = 0; rep < 4; rep++) {
                cpa16(adst[rep] + so, A + (size_t)arow[rep] * 1024 + kc + 4 * cj[rep]);
                cpa16(wdst[rep] + so, W + (size_t)(bn + cm[rep]) * 1024 + kc + 4 * cj[rep]);
            }
        }
        CP_COMMIT();
        CP_WAIT(1);
        __syncthreads();

        const float* As = smf + (c & 1) * STG;
        const float* Ws = As + 4096;
#pragma unroll
        for (int kk = 0; kk < 4; kk++) {
            int kl = (kk * 8 + tig) ^ swz;
            int kh = (kk * 8 + tig + 4) ^ swz;
            uint32_t a[4][4], b[4][2];
#pragma unroll
            for (int mi = 0; mi < 4; mi++) {
                int base = (wm * 64 + mi * 16 + g) * 32;
                a[mi][0] = f2tf32(As[base + kl]);
                a[mi][1] = f2tf32(As[base + 256 + kl]);
                a[mi][2] = f2tf32(As[base + kh]);
                a[mi][3] = f2tf32(As[base + 256 + kh]);
            }
#pragma unroll
            for (int ni = 0; ni < 4; ni++) {
                int nb = (wn * 32 + ni * 8 + g) * 32;
                b[ni][0] = f2tf32(Ws[nb + kl]);
                b[ni][1] = f2tf32(Ws[nb + kh]);
            }
#pragma unroll
            for (int mi = 0; mi < 4; mi++)
#pragma unroll
                for (int ni = 0; ni < 4; ni++)
                    mma8(acc[mi][ni], a[mi], b[ni]);
        }
        __syncthreads();
    }

    // epilogue: + b1 + b2
#pragma unroll
    for (int ni = 0; ni < 4; ni++) {
        int nc = bn + wn * 32 + ni * 8 + 2 * tig;
        float bia0 = b1[nc] + b2[nc];
        float bia1 = b1[nc + 1] + b2[nc + 1];
#pragma unroll
        for (int mi = 0; mi < 4; mi++) {
            int mr = bm + wm * 64 + mi * 16 + g;
            *(float2*)(C + (size_t)mr * GATES + nc) =
                make_float2(acc[mi][ni][0] + bia0, acc[mi][ni][1] + bia1);
            *(float2*)(C + (size_t)(mr + 8) * GATES + nc) =
                make_float2(acc[mi][ni][2] + bia0, acc[mi][ni][3] + bia1);
        }
    }
}
#define SGEMM_SMEM (2 * STG * 4)

// ---------------- persistent LSTM recurrence (tf32 mma) ---------------------
// (unchanged from R2)
#define PW 40
#define PH 68
#define REC_SMEM ((1024*PW + 2*64*PH) * 4)

__global__ __launch_bounds__(128, 1) void lstm_rec(
    const float* __restrict__ xp, const float* __restrict__ whh,
    float* hist, int mode, float* __restrict__ out_h, float* __restrict__ out_c)
{
    extern __shared__ float sm[];
    uint32_t* ws = (uint32_t*)sm;              // [1024][PW] tf32
    float* hs = sm + 1024 * PW;                // [2][64][PH]
    const uint32_t hs_u32 = (uint32_t)__cvta_generic_to_shared(hs);

    const int tid = threadIdx.x;
    const int warp = tid >> 5, lane = tid & 31;
    const int g = lane >> 2, tig = lane & 3;
    const int j0 = blockIdx.x * 8;
    const int mrow = warp * 16 + g;            // batch rows: mrow, mrow+8

    // preload weights (tf32) once
    {
        int c = tid & 31;                               // gate-col 0..31
        int kq = tid >> 5;                              // k quarter
        int wrow = ((c >> 3) << 10) + j0 + (c & 7);     // global gate col
        const float4* w4 = (const float4*)(whh + (size_t)wrow * 1024);
        for (int k4 = kq * 64; k4 < kq * 64 + 64; k4++) {
            float4 v = w4[k4];
            int k = 4 * k4;
            ws[(k+0)*PW + c] = f2tf32(v.x);
            ws[(k+1)*PW + c] = f2tf32(v.y);
            ws[(k+2)*PW + c] = f2tf32(v.z);
            ws[(k+3)*PW + c] = f2tf32(v.w);
        }
    }
    __syncthreads();

    float cst[4] = {0.f, 0.f, 0.f, 0.f};   // c-state: [ri*2+ci]
    const int sb = tid & 63;                // staging batch row
    const int skh = (tid >> 6) * 32;        // staging k half

    for (int t = 0; t < SEQL; t++) {
        const float* xpt = xp + (size_t)t * BATCH * GATES;
        float2 xv[8];
#pragma unroll
        for (int gi = 0; gi < 4; gi++)
#pragma unroll
            for (int ri = 0; ri < 2; ri++) {
                int b = mrow + ri * 8;
                xv[gi*2+ri] = *(const float2*)(xpt + (size_t)b * GATES + gi * 1024 + j0 + 2 * tig);
            }

        float acc[4][4];
#pragma unroll
        for (int ni = 0; ni < 4; ni++)
#pragma unroll
            for (int r = 0; r < 4; r++) acc[ni][r] = 0.f;

        if (t > 0) {
            const float* hp = (mode == 0) ? hist + (size_t)(t-1) * BH
                                          : hist + (size_t)((t-1) & 1) * BH;
            {
                uint32_t s = hs_u32 + (sb * PH + skh) * 4;
                const float* gp = hp + (size_t)sb * 1024 + skh;
#pragma unroll
                for (int i = 0; i < 8; i++) cpa16(s + 16 * i, gp + 4 * i);
                CP_COMMIT();
            }
            for (int kc = 0; kc < 16; kc++) {
                if (kc < 15) {
                    int buf = (kc + 1) & 1;
                    uint32_t s = hs_u32 + (buf * 64 * PH + sb * PH + skh) * 4;
                    const float* gp = hp + (size_t)sb * 1024 + (kc + 1) * 64 + skh;
#pragma unroll
                    for (int i = 0; i < 8; i++) cpa16(s + 16 * i, gp + 4 * i);
                    CP_COMMIT();
                    CP_WAIT(1);
                } else {
                    CP_WAIT(0);
                }
                __syncthreads();
                const float* hb = hs + (kc & 1) * 64 * PH;
                const int kg = kc * 64;
#pragma unroll
                for (int kk = 0; kk < 8; kk++) {
                    int klo = kk * 8 + tig, khi = klo + 4;
                    uint32_t a[4];
                    a[0] = __float_as_uint(hb[mrow * PH + klo]);
                    a[1] = __float_as_uint(hb[(mrow + 8) * PH + klo]);
                    a[2] = __float_as_uint(hb[mrow * PH + khi]);
                    a[3] = __float_as_uint(hb[(mrow + 8) * PH + khi]);
#pragma unroll
                    for (int ni = 0; ni < 4; ni++) {
                        uint32_t b[2];
                        int nc = ni * 8 + g;
                        b[0] = ws[(kg + klo) * PW + nc];
                        b[1] = ws[(kg + khi) * PW + nc];
                        mma8(acc[ni], a, b);
                    }
                }
                __syncthreads();
            }
        }

        float* hw = (mode == 0) ? hist + (size_t)t * BH
                                : hist + (size_t)(t & 1) * BH;
#pragma unroll
        for (int ri = 0; ri < 2; ri++)
#pragma unroll
            for (int ci = 0; ci < 2; ci++) {
                int r = ri * 2 + ci;
                int b = mrow + ri * 8;
                int jj = 2 * tig + ci;
                float xi = ci ? xv[0*2+ri].y : xv[0*2+ri].x;
                float xf = ci ? xv[1*2+ri].y : xv[1*2+ri].x;
                float xg = ci ? xv[2*2+ri].y : xv[2*2+ri].x;
                float xo = ci ? xv[3*2+ri].y : xv[3*2+ri].x;
                float ii = sigf(acc[0][r] + xi);
                float ff = sigf(acc[1][r] + xf);
                float gg = tanhfast(acc[2][r] + xg);
                float oo = sigf(acc[3][r] + xo);
                float cn = ff * cst[r] + ii * gg;
                float hn = oo * tanhfast(cn);
                cst[r] = cn;
                hw[(size_t)b * HID + j0 + jj] = hn;
                if (t == SEQL - 1) {
                    out_h[(size_t)b * HID + j0 + jj] = hn;
                    out_c[(size_t)b * HID + j0 + jj] = cn;
                }
            }
        gridbar(gridDim.x);
    }
}

// ---------------- launch ----------------------------------------------------
extern "C" void kernel_launch(void* const* d_in, const int* in_sizes, int n_in,
                              void* d_out, int out_size)
{
    const int*   seq  = (const int*)d_in[0];
    const float* emb  = (const float*)d_in[1];
    const float* wih0 = (const float*)d_in[2];
    const float* whh0 = (const float*)d_in[3];
    const float* bih0 = (const float*)d_in[4];
    const float* bhh0 = (const float*)d_in[5];
    const float* wih1 = (const float*)d_in[6];
    const float* whh1 = (const float*)d_in[7];
    const float* bih1 = (const float*)d_in[8];
    const float* bhh1 = (const float*)d_in[9];
    float* out = (float*)d_out;

    float *xp, *ys, *hb;
    cudaGetSymbolAddress((void**)&xp, g_xp);
    cudaGetSymbolAddress((void**)&ys, g_ys);
    cudaGetSymbolAddress((void**)&hb, g_hb);

    cudaFuncSetAttribute(sgemm_xp, cudaFuncAttributeMaxDynamicSharedMemorySize, SGEMM_SMEM);
    cudaFuncSetAttribute(lstm_rec, cudaFuncAttributeMaxDynamicSharedMemorySize, REC_SMEM);

    dim3 gg(GATES / 128, MROWS / 128);   // (32, 128)

    // out layout: [h0 | h1 | c0 | c1], each 64x1024
    sgemm_xp<<<gg, 256, SGEMM_SMEM>>>(emb, seq, wih0, bih0, bhh0, xp);
    lstm_rec<<<128, 128, REC_SMEM>>>(xp, whh0, ys, 0, out, out + 2 * BH);

    sgemm_xp<<<gg, 256, SGEMM_SMEM>>>(ys, nullptr, wih1, bih1, bhh1, xp);
    lstm_rec<<<128, 128, REC_SMEM>>>(xp, whh1, hb, 1, out + BH, out + 3 * BH);
}

// round 5
// speedup vs baseline: 1.0019x; 1.0019x over previous
#include <cuda_runtime.h>
#include <math.h>
#include <stdint.h>

#define SEQL 256
#define BATCH 64
#define HID 1024
#define GATES 4096
#define MROWS (SEQL*BATCH)      // 16384
#define BH (BATCH*HID)          // 65536

// ---------------- scratch (device globals; no cudaMalloc allowed) ----------
__device__ float g_xp[(size_t)MROWS * GATES];   // 256 MB: x-projection for one layer
__device__ float g_ys[(size_t)SEQL * BH];       // 64 MB: layer-0 h history
__device__ float g_hb[2 * BH];                  // layer-1 h ping-pong
__device__ volatile unsigned g_bar_gen;
__device__ unsigned g_bar_cnt;

// ---------------- helpers ---------------------------------------------------
__device__ __forceinline__ uint32_t f2tf32(float x) {
    uint32_t r; asm("cvt.rna.tf32.f32 %0, %1;" : "=r"(r) : "f"(x)); return r;
}
__device__ __forceinline__ void mma8(float* d, const uint32_t* a, const uint32_t* b) {
    asm volatile(
        "mma.sync.aligned.m16n8k8.row.col.f32.tf32.tf32.f32 "
        "{%0,%1,%2,%3},{%4,%5,%6,%7},{%8,%9},{%0,%1,%2,%3};"
        : "+f"(d[0]), "+f"(d[1]), "+f"(d[2]), "+f"(d[3])
        : "r"(a[0]), "r"(a[1]), "r"(a[2]), "r"(a[3]), "r"(b[0]), "r"(b[1]));
}
__device__ __forceinline__ void cpa16(uint32_t s, const void* g) {
    asm volatile("cp.async.cg.shared.global [%0], [%1], 16;" :: "r"(s), "l"(g));
}
#define CP_COMMIT() asm volatile("cp.async.commit_group;")
#define CP_WAIT(n)  asm volatile("cp.async.wait_group %0;" :: "n"(n))

__device__ __forceinline__ float sigf(float x) { return __fdividef(1.f, 1.f + __expf(-x)); }
__device__ __forceinline__ float tanhfast(float x) { return __fdividef(2.f, 1.f + __expf(-2.f * x)) - 1.f; }

// ---------------- grid barrier (all 128 blocks resident, 1/SM) --------------
__device__ __forceinline__ void gridbar(unsigned nblk) {
    __threadfence();
    __syncthreads();
    if (threadIdx.x == 0) {
        unsigned gen = g_bar_gen;
        if (atomicAdd(&g_bar_cnt, 1u) == nblk - 1u) {
            atomicExch(&g_bar_cnt, 0u);
            __threadfence();
            g_bar_gen = gen + 1u;
        } else {
            while (g_bar_gen == gen) { __nanosleep(32); }
            __threadfence();
        }
    }
    __syncthreads();
}

// ---------------- tf32 SGEMM v3: cp.async 2-stage pipelined ------------------
// C[M][4096] = gather(A)[M][1024] @ W^T + b1 + b2
// block 128x128, k-chunk 32, 256 threads (8 warps 2x4), warp tile 64x32.
// SMEM: 2 stages x [As 128x32 | Ws 128x32] fp32, XOR swizzle: elem (m,k) at
// m*32 + (k ^ ((m&7)<<2)). Fragments cvt.rna'd to tf32 in registers.
#define STG 8192   // floats per stage (As 4096 + Ws 4096)
__global__ __launch_bounds__(256, 2) void sgemm_xp(
    const float* __restrict__ A, const int* __restrict__ gidx,
    const float* __restrict__ W,
    const float* __restrict__ b1, const float* __restrict__ b2,
    float* __restrict__ C)
{
    extern __shared__ float smf[];
    const uint32_t smem_b = (uint32_t)__cvta_generic_to_shared(smf);
    const int bn = blockIdx.x * 128;
    const int bm = blockIdx.y * 128;
    const int tid = threadIdx.x;
    const int warp = tid >> 5, lane = tid & 31;
    const int g = lane >> 2, tig = lane & 3;
    const int wm = warp >> 2, wn = warp & 3;

    // per-thread copy assignment: 4 (m,j) pairs for A and W each
    int cm[4]; int cj[4]; int arow[4]; uint32_t adst[4], wdst[4];
#pragma unroll
    for (int rep = 0; rep < 4; rep++) {
        int q = tid + rep * 256;
        int m = q >> 3, j = q & 7;
        cm[rep] = m; cj[rep] = j;
        arow[rep] = gidx ? gidx[bm + m] : (bm + m);
        uint32_t off = (uint32_t)(m * 32 + ((4 * j) ^ ((m & 7) << 2)));
        adst[rep] = smem_b + off * 4;
        wdst[rep] = smem_b + (off + 4096) * 4;
    }

    float acc[4][4][4];
#pragma unroll
    for (int mi = 0; mi < 4; mi++)
#pragma unroll
        for (int ni = 0; ni < 4; ni++)
#pragma unroll
            for (int r = 0; r < 4; r++) acc[mi][ni][r] = 0.f;

    // prologue: stage chunk 0 into buffer 0
#pragma unroll
    for (int rep = 0; rep < 4; rep++) {
        cpa16(adst[rep], A + (size_t)arow[rep] * 1024 + 4 * cj[rep]);
        cpa16(wdst[rep], W + (size_t)(bn + cm[rep]) * 1024 + 4 * cj[rep]);
    }
    CP_COMMIT();

    const int swz = g << 2;
    for (int c = 0; c < 32; c++) {
        if (c + 1 < 32) {
            uint32_t so = (uint32_t)(((c + 1) & 1) * STG) * 4;
            int kc = (c + 1) * 32;
#pragma unroll
            for (int rep = 0; rep < 4; rep++) {
                cpa16(adst[rep] + so, A + (size_t)arow[rep] * 1024 + kc + 4 * cj[rep]);
                cpa16(wdst[rep] + so, W + (size_t)(bn + cm[rep]) * 1024 + kc + 4 * cj[rep]);
            }
        }
        CP_COMMIT();
        CP_WAIT(1);
        __syncthreads();

        const float* As = smf + (c & 1) * STG;
        const float* Ws = As + 4096;
#pragma unroll
        for (int kk = 0; kk < 4; kk++) {
            int kl = (kk * 8 + tig) ^ swz;
            int kh = (kk * 8 + tig + 4) ^ swz;
            uint32_t a[4][4], b[4][2];
#pragma unroll
            for (int mi = 0; mi < 4; mi++) {
                int base = (wm * 64 + mi * 16 + g) * 32;
                a[mi][0] = f2tf32(As[base + kl]);
                a[mi][1] = f2tf32(As[base + 256 + kl]);
                a[mi][2] = f2tf32(As[base + kh]);
                a[mi][3] = f2tf32(As[base + 256 + kh]);
            }
#pragma unroll
            for (int ni = 0; ni < 4; ni++) {
                int nb = (wn * 32 + ni * 8 + g) * 32;
                b[ni][0] = f2tf32(Ws[nb + kl]);
                b[ni][1] = f2tf32(Ws[nb + kh]);
            }
#pragma unroll
            for (int mi = 0; mi < 4; mi++)
#pragma unroll
                for (int ni = 0; ni < 4; ni++)
                    mma8(acc[mi][ni], a[mi], b[ni]);
        }
        __syncthreads();
    }

    // epilogue: + b1 + b2
#pragma unroll
    for (int ni = 0; ni < 4; ni++) {
        int nc = bn + wn * 32 + ni * 8 + 2 * tig;
        float bia0 = b1[nc] + b2[nc];
        float bia1 = b1[nc + 1] + b2[nc + 1];
#pragma unroll
        for (int mi = 0; mi < 4; mi++) {
            int mr = bm + wm * 64 + mi * 16 + g;
            *(float2*)(C + (size_t)mr * GATES + nc) =
                make_float2(acc[mi][ni][0] + bia0, acc[mi][ni][1] + bia1);
            *(float2*)(C + (size_t)(mr + 8) * GATES + nc) =
                make_float2(acc[mi][ni][2] + bia0, acc[mi][ni][3] + bia1);
        }
    }
}
#define SGEMM_SMEM (2 * STG * 4)

// ---------------- persistent LSTM recurrence (tf32 mma) ---------------------
// (unchanged from R2)
#define PW 40
#define PH 68
#define REC_SMEM ((1024*PW + 2*64*PH) * 4)

__global__ __launch_bounds__(128, 1) void lstm_rec(
    const float* __restrict__ xp, const float* __restrict__ whh,
    float* hist, int mode, float* __restrict__ out_h, float* __restrict__ out_c)
{
    extern __shared__ float sm[];
    uint32_t* ws = (uint32_t*)sm;              // [1024][PW] tf32
    float* hs = sm + 1024 * PW;                // [2][64][PH]
    const uint32_t hs_u32 = (uint32_t)__cvta_generic_to_shared(hs);

    const int tid = threadIdx.x;
    const int warp = tid >> 5, lane = tid & 31;
    const int g = lane >> 2, tig = lane & 3;
    const int j0 = blockIdx.x * 8;
    const int mrow = warp * 16 + g;            // batch rows: mrow, mrow+8

    // preload weights (tf32) once
    {
        int c = tid & 31;                               // gate-col 0..31
        int kq = tid >> 5;                              // k quarter
        int wrow = ((c >> 3) << 10) + j0 + (c & 7);     // global gate col
        const float4* w4 = (const float4*)(whh + (size_t)wrow * 1024);
        for (int k4 = kq * 64; k4 < kq * 64 + 64; k4++) {
            float4 v = w4[k4];
            int k = 4 * k4;
            ws[(k+0)*PW + c] = f2tf32(v.x);
            ws[(k+1)*PW + c] = f2tf32(v.y);
            ws[(k+2)*PW + c] = f2tf32(v.z);
            ws[(k+3)*PW + c] = f2tf32(v.w);
        }
    }
    __syncthreads();

    float cst[4] = {0.f, 0.f, 0.f, 0.f};   // c-state: [ri*2+ci]
    const int sb = tid & 63;                // staging batch row
    const int skh = (tid >> 6) * 32;        // staging k half

    for (int t = 0; t < SEQL; t++) {
        const float* xpt = xp + (size_t)t * BATCH * GATES;
        float2 xv[8];
#pragma unroll
        for (int gi = 0; gi < 4; gi++)
#pragma unroll
            for (int ri = 0; ri < 2; ri++) {
                int b = mrow + ri * 8;
                xv[gi*2+ri] = *(const float2*)(xpt + (size_t)b * GATES + gi * 1024 + j0 + 2 * tig);
            }

        float acc[4][4];
#pragma unroll
        for (int ni = 0; ni < 4; ni++)
#pragma unroll
            for (int r = 0; r < 4; r++) acc[ni][r] = 0.f;

        if (t > 0) {
            const float* hp = (mode == 0) ? hist + (size_t)(t-1) * BH
                                          : hist + (size_t)((t-1) & 1) * BH;
            {
                uint32_t s = hs_u32 + (sb * PH + skh) * 4;
                const float* gp = hp + (size_t)sb * 1024 + skh;
#pragma unroll
                for (int i = 0; i < 8; i++) cpa16(s + 16 * i, gp + 4 * i);
                CP_COMMIT();
            }
            for (int kc = 0; kc < 16; kc++) {
                if (kc < 15) {
                    int buf = (kc + 1) & 1;
                    uint32_t s = hs_u32 + (buf * 64 * PH + sb * PH + skh) * 4;
                    const float* gp = hp + (size_t)sb * 1024 + (kc + 1) * 64 + skh;
#pragma unroll
                    for (int i = 0; i < 8; i++) cpa16(s + 16 * i, gp + 4 * i);
                    CP_COMMIT();
                    CP_WAIT(1);
                } else {
                    CP_WAIT(0);
                }
                __syncthreads();
                const float* hb = hs + (kc & 1) * 64 * PH;
                const int kg = kc * 64;
#pragma unroll
                for (int kk = 0; kk < 8; kk++) {
                    int klo = kk * 8 + tig, khi = klo + 4;
                    uint32_t a[4];
                    a[0] = __float_as_uint(hb[mrow * PH + klo]);
                    a[1] = __float_as_uint(hb[(mrow + 8) * PH + klo]);
                    a[2] = __float_as_uint(hb[mrow * PH + khi]);
                    a[3] = __float_as_uint(hb[(mrow + 8) * PH + khi]);
#pragma unroll
                    for (int ni = 0; ni < 4; ni++) {
                        uint32_t b[2];
                        int nc = ni * 8 + g;
                        b[0] = ws[(kg + klo) * PW + nc];
                        b[1] = ws[(kg + khi) * PW + nc];
                        mma8(acc[ni], a, b);
                    }
                }
                __syncthreads();
            }
        }

        float* hw = (mode == 0) ? hist + (size_t)t * BH
                                : hist + (size_t)(t & 1) * BH;
#pragma unroll
        for (int ri = 0; ri < 2; ri++)
#pragma unroll
            for (int ci = 0; ci < 2; ci++) {
                int r = ri * 2 + ci;
                int b = mrow + ri * 8;
                int jj = 2 * tig + ci;
                float xi = ci ? xv[0*2+ri].y : xv[0*2+ri].x;
                float xf = ci ? xv[1*2+ri].y : xv[1*2+ri].x;
                float xg = ci ? xv[2*2+ri].y : xv[2*2+ri].x;
                float xo = ci ? xv[3*2+ri].y : xv[3*2+ri].x;
                float ii = sigf(acc[0][r] + xi);
                float ff = sigf(acc[1][r] + xf);
                float gg = tanhfast(acc[2][r] + xg);
                float oo = sigf(acc[3][r] + xo);
                float cn = ff * cst[r] + ii * gg;
                float hn = oo * tanhfast(cn);
                cst[r] = cn;
                hw[(size_t)b * HID + j0 + jj] = hn;
                if (t == SEQL - 1) {
                    out_h[(size_t)b * HID + j0 + jj] = hn;
                    out_c[(size_t)b * HID + j0 + jj] = cn;
                }
            }
        gridbar(gridDim.x);
    }
}

// ---------------- launch ----------------------------------------------------
extern "C" void kernel_launch(void* const* d_in, const int* in_sizes, int n_in,
                              void* d_out, int out_size)
{
    const int*   seq  = (const int*)d_in[0];
    const float* emb  = (const float*)d_in[1];
    const float* wih0 = (const float*)d_in[2];
    const float* whh0 = (const float*)d_in[3];
    const float* bih0 = (const float*)d_in[4];
    const float* bhh0 = (const float*)d_in[5];
    const float* wih1 = (const float*)d_in[6];
    const float* whh1 = (const float*)d_in[7];
    const float* bih1 = (const float*)d_in[8];
    const float* bhh1 = (const float*)d_in[9];
    float* out = (float*)d_out;

    float *xp, *ys, *hb;
    cudaGetSymbolAddress((void**)&xp, g_xp);
    cudaGetSymbolAddress((void**)&ys, g_ys);
    cudaGetSymbolAddress((void**)&hb, g_hb);

    cudaFuncSetAttribute(sgemm_xp, cudaFuncAttributeMaxDynamicSharedMemorySize, SGEMM_SMEM);
    cudaFuncSetAttribute(lstm_rec, cudaFuncAttributeMaxDynamicSharedMemorySize, REC_SMEM);

    dim3 gg(GATES / 128, MROWS / 128);   // (32, 128)

    // out layout: [h0 | h1 | c0 | c1], each 64x1024
    sgemm_xp<<<gg, 256, SGEMM_SMEM>>>(emb, seq, wih0, bih0, bhh0, xp);
    lstm_rec<<<128, 128, REC_SMEM>>>(xp, whh0, ys, 0, out, out + 2 * BH);

    sgemm_xp<<<gg, 256, SGEMM_SMEM>>>(ys, nullptr, wih1, bih1, bhh1, xp);
    lstm_rec<<<128, 128, REC_SMEM>>>(xp, whh1, hb, 1, out + BH, out + 3 * BH);
}